// round 6
// baseline (speedup 1.0000x reference)
#include <cuda_runtime.h>
#include <cstdint>
#include <cstddef>

#define RREL 8
#define DIN 64
#define DHID 128
#define DOUT 64
#define LN_EPS 1e-5f
#define NMAX 50000
#define EMAX 800000

// ---------------- scratch (static device allocations) ----------------
__device__ float g_S1[(size_t)RREL * NMAX * DIN];     // per-relation aggregated x sums [R][N][64]
__device__ float g_cnt[(size_t)NMAX * RREL];          // edge counts per (node, relation)
__device__ float g_norm[(size_t)NMAX * RREL];         // 1/cnt (0 if cnt==0)
__device__ float g_H[(size_t)NMAX * DHID];            // hidden activations [N][128] (pre then post LN, in place)
__device__ float g_T2[(size_t)9 * NMAX * DOUT];       // layer2 transforms: r<8 -> H@W2[r]; r==8 -> H@root2
__device__ float g_agg2[(size_t)NMAX * DOUT];         // layer2 aggregated messages [N][64]
__device__ int   g_idx64;                             // 1 if edge indices are int64, 0 if int32

// ---------------- helpers ----------------
__device__ __forceinline__ unsigned long long pack2(float x) {
    unsigned long long r;
    asm("mov.b64 %0, {%1, %1};" : "=l"(r) : "f"(x));
    return r;
}
__device__ __forceinline__ void fma2(unsigned long long& d, unsigned long long a, unsigned long long b) {
    asm("fma.rn.f32x2 %0, %1, %2, %0;" : "+l"(d) : "l"(a), "l"(b));
}
__device__ __forceinline__ float2 unpack2(unsigned long long v) {
    float2 f;
    asm("mov.b64 {%0, %1}, %2;" : "=f"(f.x), "=f"(f.y) : "l"(v));
    return f;
}
// Vector reduction (no return) — avoids dependence on the CUDA-header
// atomicAdd(float4*) overload; sm_90+ PTX.
__device__ __forceinline__ void red_add_f4(float* p, float4 v) {
    asm volatile("red.global.add.v4.f32 [%0], {%1, %2, %3, %4};"
                 :: "l"(p), "f"(v.x), "f"(v.y), "f"(v.z), "f"(v.w) : "memory");
}

__device__ __forceinline__ void load_edge(const void* ei, const void* et, int e, int Ee,
                                          int& s, int& d, int& r) {
    if (g_idx64) {
        const long long* p = (const long long*)ei;
        s = (int)p[e];
        d = (int)p[Ee + e];
        r = (int)((const long long*)et)[e];
    } else {
        const int* p = (const int*)ei;
        s = p[e];
        d = p[Ee + e];
        r = ((const int*)et)[e];
    }
}

// ---------------- kernels ----------------

// Detect whether edge_index is stored as int64 or int32.
// Reading the buffer as int64: true-int64 values all lie in [0, N); int32 data
// interpreted as int64 combines two random node ids -> almost surely >= 2^32.
__global__ void detect_kernel(const void* ei, int Nn) {
    __shared__ int bad;
    if (threadIdx.x == 0) bad = 0;
    __syncthreads();
    const long long* p = (const long long*)ei;
    for (int i = threadIdx.x; i < 4096; i += blockDim.x) {
        long long v = p[i];
        if (v < 0 || v >= (long long)Nn) bad = 1;
    }
    __syncthreads();
    if (threadIdx.x == 0) g_idx64 = bad ? 0 : 1;
}

// Edge pass 1: scatter x[src] into g_S1[etype][dst][:] and count edges per (dst, etype).
// 8 threads cooperate per edge (each handles 8 of the 64 floats).
__global__ void edge_scatter1(const void* ei, const void* et, const float* __restrict__ x,
                              int Nn, int Ee) {
    int t = blockIdx.x * blockDim.x + threadIdx.x;
    int e = t >> 3, sub = t & 7;
    if (e >= Ee) return;
    int s, d, r;
    load_edge(ei, et, e, Ee, s, d, r);
    const float4* xs = (const float4*)(x + (size_t)s * DIN);
    float4 v0 = __ldg(xs + sub * 2);
    float4 v1 = __ldg(xs + sub * 2 + 1);
    float* dp = &g_S1[((size_t)r * Nn + d) * DIN + sub * 8];
    red_add_f4(dp, v0);
    red_add_f4(dp + 4, v1);
    if (sub == 0) atomicAdd(&g_cnt[(size_t)d * RREL + r], 1.0f);
}

__global__ void norm_kernel(int Nn) {
    int i = blockIdx.x * blockDim.x + threadIdx.x;
    if (i >= Nn * RREL) return;
    float c = g_cnt[i];
    g_norm[i] = (c > 0.f) ? (1.0f / c) : 0.0f;
}

// GEMM1: H_pre[n][c] = sum_{r<8} (norm(n,r)*S1[r][n]) @ W1[r] + x[n] @ root1 + bias1
// Virtual A: [N x 576], virtual B: [576 x 128]. Block tile 64 nodes x 128 cols.
__global__ __launch_bounds__(256) void gemm1_kernel(const float* __restrict__ x,
                                                    const float* __restrict__ W1,
                                                    const float* __restrict__ root1,
                                                    const float* __restrict__ bias1,
                                                    int Nn) {
    __shared__ __align__(16) float As[16][68];   // [k][node], padded (68*4=272B, 16B multiple)
    __shared__ __align__(16) float Bs[16][128];  // [k][col]

    const int n0 = blockIdx.x * 64;
    const int t  = threadIdx.x;
    const int tn = t >> 5;          // 0..7  : node group (8 nodes)
    const int tc = t & 31;          // 0..31 : col group (4 cols)
    const int ln = t >> 2;          // 0..63 : A-load node
    const int lq = t & 3;           // 0..3  : A-load k quad
    const int bk = t >> 4;          // 0..15 : B-load k row
    const int bc = (t & 15) * 8;    // B-load col

    unsigned long long acc[4][4];
#pragma unroll
    for (int p = 0; p < 4; p++)
#pragma unroll
        for (int c = 0; c < 4; c++) acc[p][c] = 0ull;

    for (int kc = 0; kc < 36; kc++) {
        // --- global fetch A (with norm scaling) ---
        float4 av = make_float4(0.f, 0.f, 0.f, 0.f);
        int node = n0 + ln;
        if (kc < 32) {
            int r = kc >> 2;
            int koff = (kc & 3) * 16 + lq * 4;
            if (node < Nn) {
                av = *(const float4*)&g_S1[((size_t)r * Nn + node) * DIN + koff];
                float nm = g_norm[(size_t)node * RREL + r];
                av.x *= nm; av.y *= nm; av.z *= nm; av.w *= nm;
            }
        } else {
            int koff = (kc - 32) * 16 + lq * 4;
            if (node < Nn) av = *(const float4*)&x[(size_t)node * DIN + koff];
        }
        // --- global fetch B (virtual concat of W1 and root1) ---
        int kk = kc * 16 + bk;
        const float* bp = (kk < 512) ? &W1[(size_t)kk * DHID + bc]
                                     : &root1[(size_t)(kk - 512) * DHID + bc];
        float4 b0 = __ldg((const float4*)bp);
        float4 b1 = __ldg((const float4*)(bp + 4));

        __syncthreads();
        As[lq * 4 + 0][ln] = av.x;
        As[lq * 4 + 1][ln] = av.y;
        As[lq * 4 + 2][ln] = av.z;
        As[lq * 4 + 3][ln] = av.w;
        *(float4*)&Bs[bk][bc]     = b0;
        *(float4*)&Bs[bk][bc + 4] = b1;
        __syncthreads();

#pragma unroll
        for (int k = 0; k < 16; k++) {
            const ulonglong2* ar = (const ulonglong2*)&As[k][tn * 8];
            ulonglong2 a01 = ar[0];
            ulonglong2 a23 = ar[1];
            float4 b = *(const float4*)&Bs[k][tc * 4];
            unsigned long long bd0 = pack2(b.x), bd1 = pack2(b.y),
                               bd2 = pack2(b.z), bd3 = pack2(b.w);
            fma2(acc[0][0], a01.x, bd0); fma2(acc[0][1], a01.x, bd1);
            fma2(acc[0][2], a01.x, bd2); fma2(acc[0][3], a01.x, bd3);
            fma2(acc[1][0], a01.y, bd0); fma2(acc[1][1], a01.y, bd1);
            fma2(acc[1][2], a01.y, bd2); fma2(acc[1][3], a01.y, bd3);
            fma2(acc[2][0], a23.x, bd0); fma2(acc[2][1], a23.x, bd1);
            fma2(acc[2][2], a23.x, bd2); fma2(acc[2][3], a23.x, bd3);
            fma2(acc[3][0], a23.y, bd0); fma2(acc[3][1], a23.y, bd1);
            fma2(acc[3][2], a23.y, bd2); fma2(acc[3][3], a23.y, bd3);
        }
    }

    float4 bias = *(const float4*)&bias1[tc * 4];
#pragma unroll
    for (int p = 0; p < 4; p++) {
        float2 e0 = unpack2(acc[p][0]);
        float2 e1 = unpack2(acc[p][1]);
        float2 e2 = unpack2(acc[p][2]);
        float2 e3 = unpack2(acc[p][3]);
        int node = n0 + tn * 8 + 2 * p;
        if (node < Nn) {
            float4 o = make_float4(e0.x + bias.x, e1.x + bias.y, e2.x + bias.z, e3.x + bias.w);
            *(float4*)&g_H[(size_t)node * DHID + tc * 4] = o;
        }
        if (node + 1 < Nn) {
            float4 o = make_float4(e0.y + bias.x, e1.y + bias.y, e2.y + bias.z, e3.y + bias.w);
            *(float4*)&g_H[(size_t)(node + 1) * DHID + tc * 4] = o;
        }
    }
}

// LeakyReLU(0.2) + LayerNorm over 128 channels, in place on g_H. One warp per node.
__global__ void leaky_ln_kernel(const float* __restrict__ gamma, const float* __restrict__ beta,
                                int Nn) {
    int warp = threadIdx.x >> 5, lane = threadIdx.x & 31;
    int node = blockIdx.x * 8 + warp;
    if (node >= Nn) return;
    float4 v = *(float4*)&g_H[(size_t)node * DHID + lane * 4];
    v.x = v.x >= 0.f ? v.x : 0.2f * v.x;
    v.y = v.y >= 0.f ? v.y : 0.2f * v.y;
    v.z = v.z >= 0.f ? v.z : 0.2f * v.z;
    v.w = v.w >= 0.f ? v.w : 0.2f * v.w;
    float s = v.x + v.y + v.z + v.w;
#pragma unroll
    for (int o = 16; o; o >>= 1) s += __shfl_xor_sync(0xffffffffu, s, o);
    float mu = s * (1.0f / 128.0f);
    float dx = v.x - mu, dy = v.y - mu, dz = v.z - mu, dw = v.w - mu;
    float q = dx * dx + dy * dy + dz * dz + dw * dw;
#pragma unroll
    for (int o = 16; o; o >>= 1) q += __shfl_xor_sync(0xffffffffu, q, o);
    float rs = rsqrtf(q * (1.0f / 128.0f) + LN_EPS);
    float4 g = *(const float4*)&gamma[lane * 4];
    float4 be = *(const float4*)&beta[lane * 4];
    float4 o4 = make_float4(dx * rs * g.x + be.x, dy * rs * g.y + be.y,
                            dz * rs * g.z + be.z, dw * rs * g.w + be.w);
    *(float4*)&g_H[(size_t)node * DHID + lane * 4] = o4;
}

// GEMM2: for r in [0,9): T2[r] = H @ (r<8 ? W2[r] : root2). Block tile 128 nodes x 64 cols.
__global__ __launch_bounds__(256) void gemm2_kernel(const float* __restrict__ W2,
                                                    const float* __restrict__ root2,
                                                    int Nn) {
    __shared__ __align__(16) float As[16][132];  // [k][node], 132*4=528B (16B multiple)
    __shared__ __align__(16) float Bs[16][64];

    const int n0 = blockIdx.x * 128;
    const int r  = blockIdx.y;          // 0..8
    const int t  = threadIdx.x;
    const int tn = t >> 4;              // 0..15 : node group (8 nodes)
    const int tc = t & 15;              // 0..15 : col group (4 cols)
    const int ln = t >> 1;              // 0..127: A-load node
    const int lh = (t & 1) * 8;         // A-load k half
    const int bk = t >> 4;              // 0..15 : B-load k row
    const int bc = (t & 15) * 4;        // B-load col

    unsigned long long acc[4][4];
#pragma unroll
    for (int p = 0; p < 4; p++)
#pragma unroll
        for (int c = 0; c < 4; c++) acc[p][c] = 0ull;

    for (int kc = 0; kc < 8; kc++) {
        int koff = kc * 16;
        float4 a0 = make_float4(0.f, 0.f, 0.f, 0.f), a1 = a0;
        int node = n0 + ln;
        if (node < Nn) {
            a0 = *(const float4*)&g_H[(size_t)node * DHID + koff + lh];
            a1 = *(const float4*)&g_H[(size_t)node * DHID + koff + lh + 4];
        }
        int kk = koff + bk;
        const float* bp = (r < 8) ? &W2[((size_t)r * DHID + kk) * DOUT + bc]
                                  : &root2[(size_t)kk * DOUT + bc];
        float4 bv = __ldg((const float4*)bp);

        __syncthreads();
        As[lh + 0][ln] = a0.x; As[lh + 1][ln] = a0.y;
        As[lh + 2][ln] = a0.z; As[lh + 3][ln] = a0.w;
        As[lh + 4][ln] = a1.x; As[lh + 5][ln] = a1.y;
        As[lh + 6][ln] = a1.z; As[lh + 7][ln] = a1.w;
        *(float4*)&Bs[bk][bc] = bv;
        __syncthreads();

#pragma unroll
        for (int k = 0; k < 16; k++) {
            const ulonglong2* ar = (const ulonglong2*)&As[k][tn * 8];
            ulonglong2 a01 = ar[0];
            ulonglong2 a23 = ar[1];
            float4 b = *(const float4*)&Bs[k][tc * 4];
            unsigned long long bd0 = pack2(b.x), bd1 = pack2(b.y),
                               bd2 = pack2(b.z), bd3 = pack2(b.w);
            fma2(acc[0][0], a01.x, bd0); fma2(acc[0][1], a01.x, bd1);
            fma2(acc[0][2], a01.x, bd2); fma2(acc[0][3], a01.x, bd3);
            fma2(acc[1][0], a01.y, bd0); fma2(acc[1][1], a01.y, bd1);
            fma2(acc[1][2], a01.y, bd2); fma2(acc[1][3], a01.y, bd3);
            fma2(acc[2][0], a23.x, bd0); fma2(acc[2][1], a23.x, bd1);
            fma2(acc[2][2], a23.x, bd2); fma2(acc[2][3], a23.x, bd3);
            fma2(acc[3][0], a23.y, bd0); fma2(acc[3][1], a23.y, bd1);
            fma2(acc[3][2], a23.y, bd2); fma2(acc[3][3], a23.y, bd3);
        }
    }

#pragma unroll
    for (int p = 0; p < 4; p++) {
        float2 e0 = unpack2(acc[p][0]);
        float2 e1 = unpack2(acc[p][1]);
        float2 e2 = unpack2(acc[p][2]);
        float2 e3 = unpack2(acc[p][3]);
        int node = n0 + tn * 8 + 2 * p;
        if (node < Nn) {
            float4 o = make_float4(e0.x, e1.x, e2.x, e3.x);
            *(float4*)&g_T2[((size_t)r * Nn + node) * DOUT + tc * 4] = o;
        }
        if (node + 1 < Nn) {
            float4 o = make_float4(e0.y, e1.y, e2.y, e3.y);
            *(float4*)&g_T2[((size_t)r * Nn + node + 1) * DOUT + tc * 4] = o;
        }
    }
}

// Edge pass 2: agg2[dst] += norm(dst,etype) * T2[etype][src]. 8 threads per edge.
__global__ void edge_scatter2(const void* ei, const void* et, int Nn, int Ee) {
    int t = blockIdx.x * blockDim.x + threadIdx.x;
    int e = t >> 3, sub = t & 7;
    if (e >= Ee) return;
    int s, d, r;
    load_edge(ei, et, e, Ee, s, d, r);
    float nrm = g_norm[(size_t)d * RREL + r];
    const float4* ms = (const float4*)&g_T2[((size_t)r * Nn + s) * DOUT];
    float4 v0 = __ldg(ms + sub * 2);
    float4 v1 = __ldg(ms + sub * 2 + 1);
    v0.x *= nrm; v0.y *= nrm; v0.z *= nrm; v0.w *= nrm;
    v1.x *= nrm; v1.y *= nrm; v1.z *= nrm; v1.w *= nrm;
    float* dp = &g_agg2[(size_t)d * DOUT + sub * 8];
    red_add_f4(dp, v0);
    red_add_f4(dp + 4, v1);
}

// Final: out = LN(agg2 + H@root2 (=T2[8]) + bias2). One warp per node (64 cols, 2 per lane).
__global__ void final_ln_kernel(const float* __restrict__ bias2, const float* __restrict__ gamma2,
                                const float* __restrict__ beta2, float* __restrict__ out, int Nn) {
    int warp = threadIdx.x >> 5, lane = threadIdx.x & 31;
    int node = blockIdx.x * 8 + warp;
    if (node >= Nn) return;
    size_t base = (size_t)node * DOUT + lane * 2;
    float2 a   = *(const float2*)&g_agg2[base];
    float2 dct = *(const float2*)&g_T2[((size_t)8 * Nn) * DOUT + base];
    float2 bb  = *(const float2*)&bias2[lane * 2];
    float x0 = a.x + dct.x + bb.x;
    float x1 = a.y + dct.y + bb.y;
    float s = x0 + x1;
#pragma unroll
    for (int o = 16; o; o >>= 1) s += __shfl_xor_sync(0xffffffffu, s, o);
    float mu = s * (1.0f / 64.0f);
    float d0 = x0 - mu, d1 = x1 - mu;
    float q = d0 * d0 + d1 * d1;
#pragma unroll
    for (int o = 16; o; o >>= 1) q += __shfl_xor_sync(0xffffffffu, q, o);
    float rs = rsqrtf(q * (1.0f / 64.0f) + LN_EPS);
    float2 g  = *(const float2*)&gamma2[lane * 2];
    float2 be = *(const float2*)&beta2[lane * 2];
    float2 o2 = make_float2(d0 * rs * g.x + be.x, d1 * rs * g.y + be.y);
    *(float2*)&out[base] = o2;
}

// ---------------- launcher ----------------
extern "C" void kernel_launch(void* const* d_in, const int* in_sizes, int n_in,
                              void* d_out, int out_size) {
    const float* x      = (const float*)d_in[0];
    const void*  ei     = d_in[1];
    const void*  et     = d_in[2];
    const float* W1     = (const float*)d_in[3];
    const float* root1  = (const float*)d_in[4];
    const float* bias1  = (const float*)d_in[5];
    const float* gamma1 = (const float*)d_in[6];
    const float* beta1  = (const float*)d_in[7];
    const float* W2     = (const float*)d_in[8];
    const float* root2  = (const float*)d_in[9];
    const float* bias2  = (const float*)d_in[10];
    const float* gamma2 = (const float*)d_in[11];
    const float* beta2  = (const float*)d_in[12];
    float* out = (float*)d_out;

    int Nn = in_sizes[0] / DIN;   // 50000
    int Ee = in_sizes[2];         // 800000

    void *pS1 = nullptr, *pcnt = nullptr, *pagg = nullptr;
    cudaGetSymbolAddress(&pS1, g_S1);
    cudaGetSymbolAddress(&pcnt, g_cnt);
    cudaGetSymbolAddress(&pagg, g_agg2);
    cudaMemsetAsync(pS1, 0, (size_t)RREL * Nn * DIN * sizeof(float), 0);
    cudaMemsetAsync(pcnt, 0, (size_t)Nn * RREL * sizeof(float), 0);
    cudaMemsetAsync(pagg, 0, (size_t)Nn * DOUT * sizeof(float), 0);

    detect_kernel<<<1, 256>>>(ei, Nn);
    edge_scatter1<<<(Ee * 8 + 255) / 256, 256>>>(ei, et, x, Nn, Ee);
    norm_kernel<<<(Nn * RREL + 255) / 256, 256>>>(Nn);
    gemm1_kernel<<<(Nn + 63) / 64, 256>>>(x, W1, root1, bias1, Nn);
    leaky_ln_kernel<<<(Nn + 7) / 8, 256>>>(gamma1, beta1, Nn);
    gemm2_kernel<<<dim3((Nn + 127) / 128, 9), 256>>>(W2, root2, Nn);
    edge_scatter2<<<(Ee * 8 + 255) / 256, 256>>>(ei, et, Nn, Ee);
    final_ln_kernel<<<(Nn + 7) / 8, 256>>>(bias2, gamma2, beta2, out, Nn);
}

// round 16
// speedup vs baseline: 1.0473x; 1.0473x over previous
#include <cuda_runtime.h>
#include <cstdint>
#include <cstddef>

#define RREL 8
#define DIN 64
#define DHID 128
#define DOUT 64
#define LN_EPS 1e-5f
#define NMAX 50000
#define EMAX 800000

// ---------------- scratch (static device allocations) ----------------
__device__ float g_S1[(size_t)RREL * NMAX * DIN];     // per-relation aggregated x sums [R][N][64]
__device__ float g_cnt[(size_t)NMAX * RREL];          // edge counts per (node, relation)
__device__ float g_H[(size_t)NMAX * DHID];            // hidden activations post-LN [N][128]
__device__ float g_T2[(size_t)9 * NMAX * DOUT];       // layer2 transforms: r<8 -> H@W2[r]; r==8 -> H@root2
__device__ float g_agg2[(size_t)NMAX * DOUT];         // layer2 aggregated messages [N][64]
__device__ int   g_idx64;                             // 1 if edge indices are int64, 0 if int32

// ---------------- helpers ----------------
__device__ __forceinline__ unsigned long long pack2(float x) {
    unsigned long long r;
    asm("mov.b64 %0, {%1, %1};" : "=l"(r) : "f"(x));
    return r;
}
__device__ __forceinline__ void fma2(unsigned long long& d, unsigned long long a, unsigned long long b) {
    asm("fma.rn.f32x2 %0, %1, %2, %0;" : "+l"(d) : "l"(a), "l"(b));
}
__device__ __forceinline__ float2 unpack2(unsigned long long v) {
    float2 f;
    asm("mov.b64 {%0, %1}, %2;" : "=f"(f.x), "=f"(f.y) : "l"(v));
    return f;
}
__device__ __forceinline__ void red_add_f4(float* p, float4 v) {
    asm volatile("red.global.add.v4.f32 [%0], {%1, %2, %3, %4};"
                 :: "l"(p), "f"(v.x), "f"(v.y), "f"(v.z), "f"(v.w) : "memory");
}
__device__ __forceinline__ float lrelu(float v) { return v >= 0.f ? v : 0.2f * v; }

__device__ __forceinline__ void load_edge(const void* ei, const void* et, int e, int Ee,
                                          int& s, int& d, int& r) {
    if (g_idx64) {
        const long long* p = (const long long*)ei;
        s = (int)p[e];
        d = (int)p[Ee + e];
        r = (int)((const long long*)et)[e];
    } else {
        const int* p = (const int*)ei;
        s = p[e];
        d = p[Ee + e];
        r = ((const int*)et)[e];
    }
}

// ---------------- kernels ----------------

__global__ void detect_kernel(const void* ei, int Nn) {
    __shared__ int bad;
    if (threadIdx.x == 0) bad = 0;
    __syncthreads();
    const long long* p = (const long long*)ei;
    for (int i = threadIdx.x; i < 4096; i += blockDim.x) {
        long long v = p[i];
        if (v < 0 || v >= (long long)Nn) bad = 1;
    }
    __syncthreads();
    if (threadIdx.x == 0) g_idx64 = bad ? 0 : 1;
}

// Edge pass 1: scatter x[src] into g_S1[etype][dst][:] and count edges per (dst, etype).
__global__ void edge_scatter1(const void* ei, const void* et, const float* __restrict__ x,
                              int Nn, int Ee) {
    int t = blockIdx.x * blockDim.x + threadIdx.x;
    int e = t >> 3, sub = t & 7;
    if (e >= Ee) return;
    int s, d, r;
    load_edge(ei, et, e, Ee, s, d, r);
    const float4* xs = (const float4*)(x + (size_t)s * DIN);
    float4 v0 = __ldg(xs + sub * 2);
    float4 v1 = __ldg(xs + sub * 2 + 1);
    float* dp = &g_S1[((size_t)r * Nn + d) * DIN + sub * 8];
    red_add_f4(dp, v0);
    red_add_f4(dp + 4, v1);
    if (sub == 0) atomicAdd(&g_cnt[(size_t)d * RREL + r], 1.0f);
}

// GEMM1 + bias + LeakyReLU + LayerNorm fused.
// H[n][c] = LN( sum_{r<8} (S1[r][n]/cnt(n,r)) @ W1[r] + x[n] @ root1 + bias1 )
// Virtual A: [N x 576], virtual B: [576 x 128]. Block tile 64 nodes x 128 cols.
// Double-buffered smem, one barrier per k-chunk.
__global__ __launch_bounds__(256) void gemm1_kernel(const float* __restrict__ x,
                                                    const float* __restrict__ W1,
                                                    const float* __restrict__ root1,
                                                    const float* __restrict__ bias1,
                                                    const float* __restrict__ gamma1,
                                                    const float* __restrict__ beta1,
                                                    int Nn) {
    __shared__ __align__(16) float As[2][16][68];
    __shared__ __align__(16) float Bs[2][16][128];

    const int n0 = blockIdx.x * 64;
    const int t  = threadIdx.x;
    const int tn = t >> 5;          // 0..7  : node group (8 nodes) == warp id
    const int tc = t & 31;          // 0..31 : col group (4 cols)   == lane id
    const int ln = t >> 2;          // 0..63 : A-load node
    const int lq = t & 3;           // 0..3  : A-load k quad
    const int bk = t >> 4;          // 0..15 : B-load k row
    const int bc = (t & 15) * 8;    // B-load col

    const int nodeA = n0 + ln;

    unsigned long long acc[4][4];
#pragma unroll
    for (int p = 0; p < 4; p++)
#pragma unroll
        for (int c = 0; c < 4; c++) acc[p][c] = 0ull;

    // ---- prefetch helpers (register path) ----
    auto fetchA = [&](int kc, float4& av) {
        av = make_float4(0.f, 0.f, 0.f, 0.f);
        if (nodeA < Nn) {
            if (kc < 32) {
                int r = kc >> 2;
                int koff = (kc & 3) * 16 + lq * 4;
                av = *(const float4*)&g_S1[((size_t)r * Nn + nodeA) * DIN + koff];
                float c = g_cnt[(size_t)nodeA * RREL + r];
                float nm = (c > 0.f) ? __frcp_rn(c) : 0.f;
                av.x *= nm; av.y *= nm; av.z *= nm; av.w *= nm;
            } else {
                int koff = (kc - 32) * 16 + lq * 4;
                av = *(const float4*)&x[(size_t)nodeA * DIN + koff];
            }
        }
    };
    auto fetchB = [&](int kc, float4& b0, float4& b1) {
        int kk = kc * 16 + bk;
        const float* bp = (kk < 512) ? &W1[(size_t)kk * DHID + bc]
                                     : &root1[(size_t)(kk - 512) * DHID + bc];
        b0 = __ldg((const float4*)bp);
        b1 = __ldg((const float4*)(bp + 4));
    };
    auto stash = [&](int buf, const float4& av, const float4& b0, const float4& b1) {
        As[buf][lq * 4 + 0][ln] = av.x;
        As[buf][lq * 4 + 1][ln] = av.y;
        As[buf][lq * 4 + 2][ln] = av.z;
        As[buf][lq * 4 + 3][ln] = av.w;
        *(float4*)&Bs[buf][bk][bc]     = b0;
        *(float4*)&Bs[buf][bk][bc + 4] = b1;
    };

    {   // prologue: fill buffer 0
        float4 av, b0, b1;
        fetchA(0, av); fetchB(0, b0, b1);
        stash(0, av, b0, b1);
    }
    __syncthreads();

    int cur = 0;
    for (int kc = 0; kc < 36; kc++) {
        float4 nav, nb0, nb1;
        if (kc + 1 < 36) { fetchA(kc + 1, nav); fetchB(kc + 1, nb0, nb1); }

#pragma unroll
        for (int k = 0; k < 16; k++) {
            const ulonglong2* ar = (const ulonglong2*)&As[cur][k][tn * 8];
            ulonglong2 a01 = ar[0];
            ulonglong2 a23 = ar[1];
            float4 b = *(const float4*)&Bs[cur][k][tc * 4];
            unsigned long long bd0 = pack2(b.x), bd1 = pack2(b.y),
                               bd2 = pack2(b.z), bd3 = pack2(b.w);
            fma2(acc[0][0], a01.x, bd0); fma2(acc[0][1], a01.x, bd1);
            fma2(acc[0][2], a01.x, bd2); fma2(acc[0][3], a01.x, bd3);
            fma2(acc[1][0], a01.y, bd0); fma2(acc[1][1], a01.y, bd1);
            fma2(acc[1][2], a01.y, bd2); fma2(acc[1][3], a01.y, bd3);
            fma2(acc[2][0], a23.x, bd0); fma2(acc[2][1], a23.x, bd1);
            fma2(acc[2][2], a23.x, bd2); fma2(acc[2][3], a23.x, bd3);
            fma2(acc[3][0], a23.y, bd0); fma2(acc[3][1], a23.y, bd1);
            fma2(acc[3][2], a23.y, bd2); fma2(acc[3][3], a23.y, bd3);
        }

        if (kc + 1 < 36) stash(cur ^ 1, nav, nb0, nb1);
        __syncthreads();
        cur ^= 1;
    }

    // ---- fused epilogue: bias + LeakyReLU + LayerNorm (per-node, within warp) ----
    float4 bias = *(const float4*)&bias1[tc * 4];
    float4 gam  = *(const float4*)&gamma1[tc * 4];
    float4 bet  = *(const float4*)&beta1[tc * 4];

#pragma unroll
    for (int p = 0; p < 4; p++) {
        float2 e0 = unpack2(acc[p][0]);
        float2 e1 = unpack2(acc[p][1]);
        float2 e2 = unpack2(acc[p][2]);
        float2 e3 = unpack2(acc[p][3]);
        // node a (x-lane), node b (y-lane); this warp holds all 128 cols of both.
        float xa0 = lrelu(e0.x + bias.x), xa1 = lrelu(e1.x + bias.y);
        float xa2 = lrelu(e2.x + bias.z), xa3 = lrelu(e3.x + bias.w);
        float xb0 = lrelu(e0.y + bias.x), xb1 = lrelu(e1.y + bias.y);
        float xb2 = lrelu(e2.y + bias.z), xb3 = lrelu(e3.y + bias.w);

        float sa = xa0 + xa1 + xa2 + xa3;
        float sb = xb0 + xb1 + xb2 + xb3;
#pragma unroll
        for (int o = 16; o; o >>= 1) {
            sa += __shfl_xor_sync(0xffffffffu, sa, o);
            sb += __shfl_xor_sync(0xffffffffu, sb, o);
        }
        float mua = sa * (1.0f / 128.0f), mub = sb * (1.0f / 128.0f);
        float da0 = xa0 - mua, da1 = xa1 - mua, da2 = xa2 - mua, da3 = xa3 - mua;
        float db0 = xb0 - mub, db1 = xb1 - mub, db2 = xb2 - mub, db3 = xb3 - mub;
        float qa = da0 * da0 + da1 * da1 + da2 * da2 + da3 * da3;
        float qb = db0 * db0 + db1 * db1 + db2 * db2 + db3 * db3;
#pragma unroll
        for (int o = 16; o; o >>= 1) {
            qa += __shfl_xor_sync(0xffffffffu, qa, o);
            qb += __shfl_xor_sync(0xffffffffu, qb, o);
        }
        float rsa = rsqrtf(qa * (1.0f / 128.0f) + LN_EPS);
        float rsb = rsqrtf(qb * (1.0f / 128.0f) + LN_EPS);

        int node = n0 + tn * 8 + 2 * p;
        if (node < Nn) {
            float4 o4 = make_float4(da0 * rsa * gam.x + bet.x, da1 * rsa * gam.y + bet.y,
                                    da2 * rsa * gam.z + bet.z, da3 * rsa * gam.w + bet.w);
            *(float4*)&g_H[(size_t)node * DHID + tc * 4] = o4;
        }
        if (node + 1 < Nn) {
            float4 o4 = make_float4(db0 * rsb * gam.x + bet.x, db1 * rsb * gam.y + bet.y,
                                    db2 * rsb * gam.z + bet.z, db3 * rsb * gam.w + bet.w);
            *(float4*)&g_H[(size_t)(node + 1) * DHID + tc * 4] = o4;
        }
    }
}

// GEMM2: for r in [0,9): T2[r] = H @ (r<8 ? W2[r] : root2). Block tile 128 nodes x 64 cols.
// Double-buffered smem, one barrier per k-chunk.
__global__ __launch_bounds__(256) void gemm2_kernel(const float* __restrict__ W2,
                                                    const float* __restrict__ root2,
                                                    int Nn) {
    __shared__ __align__(16) float As[2][16][132];
    __shared__ __align__(16) float Bs[2][16][64];

    const int n0 = blockIdx.x * 128;
    const int r  = blockIdx.y;          // 0..8
    const int t  = threadIdx.x;
    const int tn = t >> 4;              // 0..15 : node group (8 nodes)
    const int tc = t & 15;              // 0..15 : col group (4 cols)
    const int ln = t >> 1;              // 0..127: A-load node
    const int lh = (t & 1) * 8;         // A-load k half
    const int bk = t >> 4;              // 0..15 : B-load k row
    const int bc = (t & 15) * 4;        // B-load col

    const int nodeA = n0 + ln;

    unsigned long long acc[4][4];
#pragma unroll
    for (int p = 0; p < 4; p++)
#pragma unroll
        for (int c = 0; c < 4; c++) acc[p][c] = 0ull;

    auto fetch = [&](int kc, float4& a0, float4& a1, float4& bv) {
        int koff = kc * 16;
        a0 = make_float4(0.f, 0.f, 0.f, 0.f); a1 = a0;
        if (nodeA < Nn) {
            a0 = *(const float4*)&g_H[(size_t)nodeA * DHID + koff + lh];
            a1 = *(const float4*)&g_H[(size_t)nodeA * DHID + koff + lh + 4];
        }
        int kk = koff + bk;
        const float* bp = (r < 8) ? &W2[((size_t)r * DHID + kk) * DOUT + bc]
                                  : &root2[(size_t)kk * DOUT + bc];
        bv = __ldg((const float4*)bp);
    };
    auto stash = [&](int buf, const float4& a0, const float4& a1, const float4& bv) {
        As[buf][lh + 0][ln] = a0.x; As[buf][lh + 1][ln] = a0.y;
        As[buf][lh + 2][ln] = a0.z; As[buf][lh + 3][ln] = a0.w;
        As[buf][lh + 4][ln] = a1.x; As[buf][lh + 5][ln] = a1.y;
        As[buf][lh + 6][ln] = a1.z; As[buf][lh + 7][ln] = a1.w;
        *(float4*)&Bs[buf][bk][bc] = bv;
    };

    {
        float4 a0, a1, bv;
        fetch(0, a0, a1, bv);
        stash(0, a0, a1, bv);
    }
    __syncthreads();

    int cur = 0;
    for (int kc = 0; kc < 8; kc++) {
        float4 na0, na1, nbv;
        if (kc + 1 < 8) fetch(kc + 1, na0, na1, nbv);

#pragma unroll
        for (int k = 0; k < 16; k++) {
            const ulonglong2* ar = (const ulonglong2*)&As[cur][k][tn * 8];
            ulonglong2 a01 = ar[0];
            ulonglong2 a23 = ar[1];
            float4 b = *(const float4*)&Bs[cur][k][tc * 4];
            unsigned long long bd0 = pack2(b.x), bd1 = pack2(b.y),
                               bd2 = pack2(b.z), bd3 = pack2(b.w);
            fma2(acc[0][0], a01.x, bd0); fma2(acc[0][1], a01.x, bd1);
            fma2(acc[0][2], a01.x, bd2); fma2(acc[0][3], a01.x, bd3);
            fma2(acc[1][0], a01.y, bd0); fma2(acc[1][1], a01.y, bd1);
            fma2(acc[1][2], a01.y, bd2); fma2(acc[1][3], a01.y, bd3);
            fma2(acc[2][0], a23.x, bd0); fma2(acc[2][1], a23.x, bd1);
            fma2(acc[2][2], a23.x, bd2); fma2(acc[2][3], a23.x, bd3);
            fma2(acc[3][0], a23.y, bd0); fma2(acc[3][1], a23.y, bd1);
            fma2(acc[3][2], a23.y, bd2); fma2(acc[3][3], a23.y, bd3);
        }

        if (kc + 1 < 8) stash(cur ^ 1, na0, na1, nbv);
        __syncthreads();
        cur ^= 1;
    }

#pragma unroll
    for (int p = 0; p < 4; p++) {
        float2 e0 = unpack2(acc[p][0]);
        float2 e1 = unpack2(acc[p][1]);
        float2 e2 = unpack2(acc[p][2]);
        float2 e3 = unpack2(acc[p][3]);
        int node = n0 + tn * 8 + 2 * p;
        if (node < Nn) {
            float4 o = make_float4(e0.x, e1.x, e2.x, e3.x);
            *(float4*)&g_T2[((size_t)r * Nn + node) * DOUT + tc * 4] = o;
        }
        if (node + 1 < Nn) {
            float4 o = make_float4(e0.y, e1.y, e2.y, e3.y);
            *(float4*)&g_T2[((size_t)r * Nn + node + 1) * DOUT + tc * 4] = o;
        }
    }
}

// Edge pass 2: agg2[dst] += (1/cnt(dst,etype)) * T2[etype][src]. 8 threads per edge.
__global__ void edge_scatter2(const void* ei, const void* et, int Nn, int Ee) {
    int t = blockIdx.x * blockDim.x + threadIdx.x;
    int e = t >> 3, sub = t & 7;
    if (e >= Ee) return;
    int s, d, r;
    load_edge(ei, et, e, Ee, s, d, r);
    float c = g_cnt[(size_t)d * RREL + r];
    float nrm = (c > 0.f) ? __frcp_rn(c) : 0.f;
    const float4* ms = (const float4*)&g_T2[((size_t)r * Nn + s) * DOUT];
    float4 v0 = __ldg(ms + sub * 2);
    float4 v1 = __ldg(ms + sub * 2 + 1);
    v0.x *= nrm; v0.y *= nrm; v0.z *= nrm; v0.w *= nrm;
    v1.x *= nrm; v1.y *= nrm; v1.z *= nrm; v1.w *= nrm;
    float* dp = &g_agg2[(size_t)d * DOUT + sub * 8];
    red_add_f4(dp, v0);
    red_add_f4(dp + 4, v1);
}

// Final: out = LN(agg2 + H@root2 (=T2[8]) + bias2). One warp per node (64 cols, 2 per lane).
__global__ void final_ln_kernel(const float* __restrict__ bias2, const float* __restrict__ gamma2,
                                const float* __restrict__ beta2, float* __restrict__ out, int Nn) {
    int warp = threadIdx.x >> 5, lane = threadIdx.x & 31;
    int node = blockIdx.x * 8 + warp;
    if (node >= Nn) return;
    size_t base = (size_t)node * DOUT + lane * 2;
    float2 a   = *(const float2*)&g_agg2[base];
    float2 dct = *(const float2*)&g_T2[((size_t)8 * Nn) * DOUT + base];
    float2 bb  = *(const float2*)&bias2[lane * 2];
    float x0 = a.x + dct.x + bb.x;
    float x1 = a.y + dct.y + bb.y;
    float s = x0 + x1;
#pragma unroll
    for (int o = 16; o; o >>= 1) s += __shfl_xor_sync(0xffffffffu, s, o);
    float mu = s * (1.0f / 64.0f);
    float d0 = x0 - mu, d1 = x1 - mu;
    float q = d0 * d0 + d1 * d1;
#pragma unroll
    for (int o = 16; o; o >>= 1) q += __shfl_xor_sync(0xffffffffu, q, o);
    float rs = rsqrtf(q * (1.0f / 64.0f) + LN_EPS);
    float2 g  = *(const float2*)&gamma2[lane * 2];
    float2 be = *(const float2*)&beta2[lane * 2];
    float2 o2 = make_float2(d0 * rs * g.x + be.x, d1 * rs * g.y + be.y);
    *(float2*)&out[base] = o2;
}

// ---------------- launcher ----------------
extern "C" void kernel_launch(void* const* d_in, const int* in_sizes, int n_in,
                              void* d_out, int out_size) {
    const float* x      = (const float*)d_in[0];
    const void*  ei     = d_in[1];
    const void*  et     = d_in[2];
    const float* W1     = (const float*)d_in[3];
    const float* root1  = (const float*)d_in[4];
    const float* bias1  = (const float*)d_in[5];
    const float* gamma1 = (const float*)d_in[6];
    const float* beta1  = (const float*)d_in[7];
    const float* W2     = (const float*)d_in[8];
    const float* root2  = (const float*)d_in[9];
    const float* bias2  = (const float*)d_in[10];
    const float* gamma2 = (const float*)d_in[11];
    const float* beta2  = (const float*)d_in[12];
    float* out = (float*)d_out;

    int Nn = in_sizes[0] / DIN;   // 50000
    int Ee = in_sizes[2];         // 800000

    void *pS1 = nullptr, *pcnt = nullptr, *pagg = nullptr;
    cudaGetSymbolAddress(&pS1, g_S1);
    cudaGetSymbolAddress(&pcnt, g_cnt);
    cudaGetSymbolAddress(&pagg, g_agg2);
    cudaMemsetAsync(pS1, 0, (size_t)RREL * Nn * DIN * sizeof(float), 0);
    cudaMemsetAsync(pcnt, 0, (size_t)Nn * RREL * sizeof(float), 0);
    cudaMemsetAsync(pagg, 0, (size_t)Nn * DOUT * sizeof(float), 0);

    detect_kernel<<<1, 256>>>(ei, Nn);
    edge_scatter1<<<(Ee * 8 + 255) / 256, 256>>>(ei, et, x, Nn, Ee);
    gemm1_kernel<<<(Nn + 63) / 64, 256>>>(x, W1, root1, bias1, gamma1, beta1, Nn);
    gemm2_kernel<<<dim3((Nn + 127) / 128, 9), 256>>>(W2, root2, Nn);
    edge_scatter2<<<(Ee * 8 + 255) / 256, 256>>>(ei, et, Nn, Ee);
    final_ln_kernel<<<(Nn + 7) / 8, 256>>>(bias2, gamma2, beta2, out, Nn);
}